// round 13
// baseline (speedup 1.0000x reference)
#include <cuda_runtime.h>
#include <cuda_bf16.h>
#include <stdint.h>

#define N_EXPERTS 20
#define DIM 32
#define MAXB (1 << 17)     // 131072
#define TPB_B 256
#define TILE 256           // tokens per compute CTA
#define CTPB 256           // 8 warps: warp w owns rows 32w..32w+31
#define ASTR 72            // tile row stride in bf16 elems (144B, conflict-free)

__device__ int g_cnt[N_EXPERTS];
__device__ int g_bucket[N_EXPERTS * MAXB];

// ---- kernel 1: fused bucket (warp-aggregated hist + claim + write) ------
__global__ void __launch_bounds__(TPB_B) k_bucket(const void* __restrict__ pos, int B) {
    __shared__ int sh[N_EXPERTS];
    __shared__ int sbase[N_EXPERTS];
    __shared__ int s_is64;

    if (threadIdx.x < N_EXPERTS) sh[threadIdx.x] = 0;
    if (threadIdx.x < 32) {
        // int64 pos => all odd 32-bit words are zero high-words (values < 20)
        int v = ((const int*)pos)[2 * threadIdx.x + 1];   // B >= 64 guaranteed
        unsigned nz = __ballot_sync(0xffffffffu, v != 0);
        if (threadIdx.x == 0) s_is64 = (nz == 0) ? 1 : 0;
    }
    __syncthreads();

    int t = blockIdx.x * TPB_B + threadIdx.x;
    bool valid = (t < B);
    int e = valid
          ? (s_is64 ? (int)((const long long*)pos)[t] : ((const int*)pos)[t])
          : -1;

    unsigned mm = __match_any_sync(0xffffffffu, e);
    int lane = threadIdx.x & 31;
    int rank = __popc(mm & ((1u << lane) - 1));
    int leader = __ffs(mm) - 1;
    int wbase = 0;
    if (lane == leader && valid) wbase = atomicAdd(&sh[e], __popc(mm));
    wbase = __shfl_sync(0xffffffffu, wbase, leader);
    int r = wbase + rank;

    __syncthreads();
    if (threadIdx.x < N_EXPERTS) {
        int c = sh[threadIdx.x];
        sbase[threadIdx.x] = c ? atomicAdd(&g_cnt[threadIdx.x], c) : 0;
    }
    __syncthreads();
    if (valid) g_bucket[e * MAXB + sbase[e] + r] = t;
}

// ---- mma.sync wrapper ----------------------------------------------------
__device__ __forceinline__ void mma16816(float* c, const uint32_t* a, const uint32_t* b) {
    asm volatile(
        "mma.sync.aligned.m16n8k16.row.col.f32.bf16.bf16.f32 "
        "{%0,%1,%2,%3}, {%4,%5,%6,%7}, {%8,%9}, {%0,%1,%2,%3};"
        : "+f"(c[0]), "+f"(c[1]), "+f"(c[2]), "+f"(c[3])
        : "r"(a[0]), "r"(a[1]), "r"(a[2]), "r"(a[3]), "r"(b[0]), "r"(b[1]));
}

// split one fp32 pair into hi/lo bf16
__device__ __forceinline__ void split2(float a, float b, uint32_t& hi, uint32_t& lo) {
    __nv_bfloat162 hp = __floats2bfloat162_rn(a, b);
    float ra = a - __bfloat162float(hp.x);
    float rb = b - __bfloat162float(hp.y);
    __nv_bfloat162 lp = __floats2bfloat162_rn(ra, rb);
    hi = *reinterpret_cast<uint32_t*>(&hp);
    lo = *reinterpret_cast<uint32_t*>(&lp);
}

// ---- kernel 2: HMMA compute (TILE=256, 8 warps, single wave) -------------
// 531 CTAs @ 47.4KB smem -> 4 CTAs/SM -> 592 slots >= grid (one wave) AND
// 32 warps/SM (8/SMSP, 2x previous): per-warp serial work is halved vs the
// two-half variant while keeping the single-wave grid. MLP prologue + quad-
// cooperative gather; one block barrier.
__global__ void __launch_bounds__(CTPB, 4) k_compute(
    const float* __restrict__ x,
    const float* __restrict__ W1, const float* __restrict__ b1,
    const float* __restrict__ W0, const float* __restrict__ b0,
    float* __restrict__ out)
{
    __shared__ __align__(16) __nv_bfloat16 sA[TILE * ASTR];      // 36864 B
    __shared__ __align__(16) __nv_bfloat16 sB1[DIM * ASTR];      // 4608 B
    __shared__ __align__(16) __nv_bfloat16 sB2[DIM * ASTR];      // 4608 B
    __shared__ __align__(16) float sb1[DIM], sb0[DIM];
    __shared__ int sTok[TILE];

    int tid = threadIdx.x;
    int l   = tid & 31;

    // ---- block -> (expert, tile): parallel load + warp scan ----
    int rem = blockIdx.x;
    int cnt = (l < N_EXPERTS) ? g_cnt[l] : 0;          // one broadcast LDG
    int nb  = (cnt + TILE - 1) / TILE;
    int s = nb;
    #pragma unroll
    for (int d = 1; d < 32; d <<= 1) {
        int u = __shfl_up_sync(0xffffffffu, s, d);
        if (l >= d) s += u;
    }
    int excl = s - nb;
    bool hit = (l < N_EXPERTS) && (rem >= excl) && (rem < excl + nb);
    unsigned hm = __ballot_sync(0xffffffffu, hit);
    if (hm == 0) return;                                // beyond total work (uniform)
    int el  = __ffs(hm) - 1;
    int e   = el;
    int n   = __shfl_sync(0xffffffffu, cnt, el);
    int base = (rem - __shfl_sync(0xffffffffu, excl, el)) * TILE;

    // ---- phase 1: all independent LDGs (weights), then the gather chain ----
    float w1r[4], w0r[4];
    #pragma unroll
    for (int q = 0; q < 4; q++) {
        int i = tid + q * CTPB;
        w1r[q] = W1[e * DIM * DIM + i];
        w0r[q] = W0[e * DIM * DIM + i];
    }
    float bv1 = 0.0f, bv0 = 0.0f;
    if (tid < DIM) {
        bv1 = b1[e * DIM + tid];
        bv0 = b0[e * DIM + tid];
    }
    int slot = base + tid;
    int tok = (slot < n) ? g_bucket[e * MAXB + slot] : -1;   // coalesced

    // quad-cooperative gather: quad (lanes l4..l4+3) owns warp rows l4..l4+3
    int t4 = l & 3;
    int l4 = l & ~3;
    int tj[4];
    #pragma unroll
    for (int j = 0; j < 4; j++)
        tj[j] = __shfl_sync(0xffffffffu, tok, l4 + j);
    float v[4][8];
    #pragma unroll
    for (int j = 0; j < 4; j++) {
        #pragma unroll
        for (int k = 0; k < 8; k++) v[j][k] = 0.0f;
        if (tj[j] >= 0) {
            const float4* xp = (const float4*)(x + (size_t)tj[j] * DIM + t4 * 8);
            float4 a = xp[0], b2 = xp[1];
            v[j][0] = a.x;  v[j][1] = a.y;  v[j][2] = a.z;  v[j][3] = a.w;
            v[j][4] = b2.x; v[j][5] = b2.y; v[j][6] = b2.z; v[j][7] = b2.w;
        }
    }

    // ---- phase 2: convert + STS (operands have landed) ----
    #pragma unroll
    for (int q = 0; q < 4; q++) {
        int i = tid + q * CTPB;
        int o = i >> 5, k = i & 31;
        __nv_bfloat16 h1 = __float2bfloat16(w1r[q]);
        sB1[o * ASTR + k]      = h1;
        sB1[o * ASTR + 32 + k] = __float2bfloat16(w1r[q] - __bfloat162float(h1));
        __nv_bfloat16 h0 = __float2bfloat16(w0r[q]);
        sB2[o * ASTR + k]      = h0;
        sB2[o * ASTR + 32 + k] = __float2bfloat16(w0r[q] - __bfloat162float(h0));
    }
    if (tid < DIM) {
        sb1[tid] = bv1;
        sb0[tid] = bv0;
    }
    sTok[tid] = tok;
    #pragma unroll
    for (int j = 0; j < 4; j++) {
        int R = (tid & ~31) + l4 + j;     // tile row
        uint32_t hi[4], lo[4];
        split2(v[j][0], v[j][1], hi[0], lo[0]);
        split2(v[j][2], v[j][3], hi[1], lo[1]);
        split2(v[j][4], v[j][5], hi[2], lo[2]);
        split2(v[j][6], v[j][7], hi[3], lo[3]);
        *(uint4*)&sA[R * ASTR + 8 * t4]      = make_uint4(hi[0], hi[1], hi[2], hi[3]);
        *(uint4*)&sA[R * ASTR + 32 + 8 * t4] = make_uint4(lo[0], lo[1], lo[2], lo[3]);
    }
    __syncthreads();   // the ONLY block barrier

    // ---- fragment geometry ----
    int w  = tid >> 5;           // 0..7, warp owns rows 32w..32w+31
    int g  = l >> 2;             // 0..7
    const int kA[6] = {0, 16, 32, 48, 0, 16};
    const int kB[6] = {0, 16, 0, 16, 32, 48};

    float acc[2][4][4];

    // ======================= layer 1 =======================
    #pragma unroll
    for (int mt = 0; mt < 2; mt++)
        #pragma unroll
        for (int nt = 0; nt < 4; nt++) {
            float2 bv = *(const float2*)&sb1[nt * 8 + 2 * t4];
            acc[mt][nt][0] = bv.x; acc[mt][nt][1] = bv.y;
            acc[mt][nt][2] = bv.x; acc[mt][nt][3] = bv.y;
        }
    #pragma unroll
    for (int ks = 0; ks < 6; ks++) {
        uint32_t bf[4][2];
        #pragma unroll
        for (int nt = 0; nt < 4; nt++) {
            bf[nt][0] = *(const uint32_t*)&sB1[(nt * 8 + g) * ASTR + kB[ks] + 2 * t4];
            bf[nt][1] = *(const uint32_t*)&sB1[(nt * 8 + g) * ASTR + kB[ks] + 2 * t4 + 8];
        }
        #pragma unroll
        for (int mt = 0; mt < 2; mt++) {
            int r0 = w * 32 + mt * 16 + g;
            uint32_t af[4];
            af[0] = *(const uint32_t*)&sA[r0       * ASTR + kA[ks] + 2 * t4];
            af[1] = *(const uint32_t*)&sA[(r0 + 8) * ASTR + kA[ks] + 2 * t4];
            af[2] = *(const uint32_t*)&sA[r0       * ASTR + kA[ks] + 2 * t4 + 8];
            af[3] = *(const uint32_t*)&sA[(r0 + 8) * ASTR + kA[ks] + 2 * t4 + 8];
            #pragma unroll
            for (int nt = 0; nt < 4; nt++) mma16816(acc[mt][nt], af, bf[nt]);
        }
    }

    // write h back into A tile (hi/lo) — warp-local rows only
    #pragma unroll
    for (int mt = 0; mt < 2; mt++) {
        int r0 = w * 32 + mt * 16 + g;
        #pragma unroll
        for (int nt = 0; nt < 4; nt++) {
            int c = nt * 8 + 2 * t4;
            uint32_t hi0, lo0, hi1, lo1;
            split2(acc[mt][nt][0], acc[mt][nt][1], hi0, lo0);
            split2(acc[mt][nt][2], acc[mt][nt][3], hi1, lo1);
            *(uint32_t*)&sA[r0 * ASTR + c]            = hi0;
            *(uint32_t*)&sA[r0 * ASTR + 32 + c]       = lo0;
            *(uint32_t*)&sA[(r0 + 8) * ASTR + c]      = hi1;
            *(uint32_t*)&sA[(r0 + 8) * ASTR + 32 + c] = lo1;
        }
    }
    __syncwarp();

    // ======================= layer 0 =======================
    #pragma unroll
    for (int mt = 0; mt < 2; mt++)
        #pragma unroll
        for (int nt = 0; nt < 4; nt++) {
            float2 bv = *(const float2*)&sb0[nt * 8 + 2 * t4];
            acc[mt][nt][0] = bv.x; acc[mt][nt][1] = bv.y;
            acc[mt][nt][2] = bv.x; acc[mt][nt][3] = bv.y;
        }
    #pragma unroll
    for (int ks = 0; ks < 6; ks++) {
        uint32_t bf[4][2];
        #pragma unroll
        for (int nt = 0; nt < 4; nt++) {
            bf[nt][0] = *(const uint32_t*)&sB2[(nt * 8 + g) * ASTR + kB[ks] + 2 * t4];
            bf[nt][1] = *(const uint32_t*)&sB2[(nt * 8 + g) * ASTR + kB[ks] + 2 * t4 + 8];
        }
        #pragma unroll
        for (int mt = 0; mt < 2; mt++) {
            int r0 = w * 32 + mt * 16 + g;
            uint32_t af[4];
            af[0] = *(const uint32_t*)&sA[r0       * ASTR + kA[ks] + 2 * t4];
            af[1] = *(const uint32_t*)&sA[(r0 + 8) * ASTR + kA[ks] + 2 * t4];
            af[2] = *(const uint32_t*)&sA[r0       * ASTR + kA[ks] + 2 * t4 + 8];
            af[3] = *(const uint32_t*)&sA[(r0 + 8) * ASTR + kA[ks] + 2 * t4 + 8];
            #pragma unroll
            for (int nt = 0; nt < 4; nt++) mma16816(acc[mt][nt], af, bf[nt]);
        }
    }

    // ---- epilogue: row sum-of-squares (4-lane bfly), normalize, store ----
    #pragma unroll
    for (int mt = 0; mt < 2; mt++) {
        int r0 = w * 32 + mt * 16 + g;
        float s0 = 0.0f, s1 = 0.0f;
        #pragma unroll
        for (int nt = 0; nt < 4; nt++) {
            s0 = fmaf(acc[mt][nt][0], acc[mt][nt][0], s0);
            s0 = fmaf(acc[mt][nt][1], acc[mt][nt][1], s0);
            s1 = fmaf(acc[mt][nt][2], acc[mt][nt][2], s1);
            s1 = fmaf(acc[mt][nt][3], acc[mt][nt][3], s1);
        }
        s0 += __shfl_xor_sync(0xffffffffu, s0, 1);
        s0 += __shfl_xor_sync(0xffffffffu, s0, 2);
        s1 += __shfl_xor_sync(0xffffffffu, s1, 1);
        s1 += __shfl_xor_sync(0xffffffffu, s1, 2);
        float inv0 = 1.0f / fmaxf(sqrtf(s0), 1e-12f);
        float inv1 = 1.0f / fmaxf(sqrtf(s1), 1e-12f);

        int u0 = sTok[r0];
        int u1 = sTok[r0 + 8];
        #pragma unroll
        for (int nt = 0; nt < 4; nt++) {
            int c = nt * 8 + 2 * t4;
            if (u0 >= 0) {
                float2 v2 = make_float2(acc[mt][nt][0] * inv0, acc[mt][nt][1] * inv0);
                *(float2*)(out + (size_t)u0 * DIM + c) = v2;
            }
            if (u1 >= 0) {
                float2 v2 = make_float2(acc[mt][nt][2] * inv1, acc[mt][nt][3] * inv1);
                *(float2*)(out + (size_t)u1 * DIM + c) = v2;
            }
        }
    }
}

// ---------------- launch -------------------------------------------------
extern "C" void kernel_launch(void* const* d_in, const int* in_sizes, int n_in,
                              void* d_out, int out_size) {
    const float* x  = (const float*)d_in[0];
    const float* W1 = (const float*)d_in[1];
    const float* b1 = (const float*)d_in[2];
    const float* W0 = (const float*)d_in[3];
    const float* b0 = (const float*)d_in[4];
    const void*  pos = d_in[5];
    float* out = (float*)d_out;

    int B = in_sizes[0] / DIM;
    if (B > MAXB) B = MAXB;
    int nblk_b = (B + TPB_B - 1) / TPB_B;
    int nblk_c = (B + TILE - 1) / TILE + N_EXPERTS - 1;

    void* cnt_ptr = nullptr;
    cudaGetSymbolAddress(&cnt_ptr, g_cnt);
    cudaMemsetAsync(cnt_ptr, 0, N_EXPERTS * sizeof(int), 0);

    k_bucket<<<nblk_b, TPB_B>>>(pos, B);
    k_compute<<<nblk_c, CTPB>>>(x, W1, b1, W0, b0, out);
}

// round 14
// speedup vs baseline: 1.0255x; 1.0255x over previous
#include <cuda_runtime.h>
#include <cuda_bf16.h>
#include <stdint.h>

#define N_EXPERTS 20
#define DIM 32
#define MAXB (1 << 17)     // 131072
#define TPB_B 256
#define TILE 128           // tokens per compute CTA
#define CTPB 128
#define ASTR 72            // tile row stride in bf16 elems (144B, conflict-free)

__device__ int g_cnt[N_EXPERTS];
__device__ int g_bucket[N_EXPERTS * MAXB];

// ---- kernel 1: fused bucket, 2 tokens/thread ----------------------------
__global__ void __launch_bounds__(TPB_B) k_bucket(const void* __restrict__ pos, int B) {
    __shared__ int sh[N_EXPERTS];
    __shared__ int sbase[N_EXPERTS];
    __shared__ int s_is64;

    if (threadIdx.x < N_EXPERTS) sh[threadIdx.x] = 0;
    if (threadIdx.x < 32) {
        // int64 pos => all odd 32-bit words are zero high-words (values < 20)
        int v = ((const int*)pos)[2 * threadIdx.x + 1];   // B >= 64 guaranteed
        unsigned nz = __ballot_sync(0xffffffffu, v != 0);
        if (threadIdx.x == 0) s_is64 = (nz == 0) ? 1 : 0;
    }
    __syncthreads();

    int lane = threadIdx.x & 31;
    int t0 = blockIdx.x * (2 * TPB_B) + threadIdx.x;
    int t1 = t0 + TPB_B;
    int e0 = -1, e1 = -1, r0 = 0, r1 = 0;
    bool v0 = (t0 < B), v1 = (t1 < B);
    if (v0) e0 = s_is64 ? (int)((const long long*)pos)[t0] : ((const int*)pos)[t0];
    if (v1) e1 = s_is64 ? (int)((const long long*)pos)[t1] : ((const int*)pos)[t1];

    {   // warp-aggregated smem hist, round 0
        unsigned mm = __match_any_sync(0xffffffffu, e0);
        int rank = __popc(mm & ((1u << lane) - 1));
        int leader = __ffs(mm) - 1;
        int wbase = 0;
        if (lane == leader && v0) wbase = atomicAdd(&sh[e0], __popc(mm));
        wbase = __shfl_sync(0xffffffffu, wbase, leader);
        r0 = wbase + rank;
    }
    {   // round 1
        unsigned mm = __match_any_sync(0xffffffffu, e1);
        int rank = __popc(mm & ((1u << lane) - 1));
        int leader = __ffs(mm) - 1;
        int wbase = 0;
        if (lane == leader && v1) wbase = atomicAdd(&sh[e1], __popc(mm));
        wbase = __shfl_sync(0xffffffffu, wbase, leader);
        r1 = wbase + rank;
    }

    __syncthreads();
    if (threadIdx.x < N_EXPERTS) {
        int c = sh[threadIdx.x];
        sbase[threadIdx.x] = c ? atomicAdd(&g_cnt[threadIdx.x], c) : 0;
    }
    __syncthreads();
    if (v0) g_bucket[e0 * MAXB + sbase[e0] + r0] = t0;
    if (v1) g_bucket[e1 * MAXB + sbase[e1] + r1] = t1;
}

// ---- mma.sync wrapper ----------------------------------------------------
__device__ __forceinline__ void mma16816(float* c, const uint32_t* a, const uint32_t* b) {
    asm volatile(
        "mma.sync.aligned.m16n8k16.row.col.f32.bf16.bf16.f32 "
        "{%0,%1,%2,%3}, {%4,%5,%6,%7}, {%8,%9}, {%0,%1,%2,%3};"
        : "+f"(c[0]), "+f"(c[1]), "+f"(c[2]), "+f"(c[3])
        : "r"(a[0]), "r"(a[1]), "r"(a[2]), "r"(a[3]), "r"(b[0]), "r"(b[1]));
}

// split one fp32 pair into hi/lo bf16
__device__ __forceinline__ void split2(float a, float b, uint32_t& hi, uint32_t& lo) {
    __nv_bfloat162 hp = __floats2bfloat162_rn(a, b);
    float ra = a - __bfloat162float(hp.x);
    float rb = b - __bfloat162float(hp.y);
    __nv_bfloat162 lp = __floats2bfloat162_rn(ra, rb);
    hi = *reinterpret_cast<uint32_t*>(&hp);
    lo = *reinterpret_cast<uint32_t*>(&lp);
}

// ---- kernel 2: HMMA compute (R11 winner + CSE-friendly product order) ----
// Product sequence reordered so duplicate smem fragment addresses are
// adjacent: kA={0,32,0,16,48,16}, kB={0,0,32,16,16,48} — same 6 products
// (hi.hi k0/k1, lo.hi k0/k1, hi.lo k0/k1), but ptxas can CSE the repeated
// LDS (A cols 0/16 and B cols 0/16 each loaded once instead of twice).
__global__ void __launch_bounds__(CTPB, 6) k_compute(
    const float* __restrict__ x,
    const float* __restrict__ W1, const float* __restrict__ b1,
    const float* __restrict__ W0, const float* __restrict__ b0,
    float* __restrict__ out)
{
    __shared__ __align__(16) __nv_bfloat16 sA[TILE * ASTR];      // 18432 B
    __shared__ __align__(16) __nv_bfloat16 sB1[DIM * ASTR];      // 4608 B
    __shared__ __align__(16) __nv_bfloat16 sB2[DIM * ASTR];      // 4608 B
    __shared__ __align__(16) float sb1[DIM], sb0[DIM];
    __shared__ int sTok[TILE];

    int tid = threadIdx.x;
    int l   = tid & 31;

    // ---- block -> (expert, tile): parallel load + warp scan ----
    int rem = blockIdx.x;
    int cnt = (l < N_EXPERTS) ? g_cnt[l] : 0;          // one broadcast LDG
    int nb  = (cnt + TILE - 1) / TILE;
    int s = nb;
    #pragma unroll
    for (int d = 1; d < 32; d <<= 1) {
        int u = __shfl_up_sync(0xffffffffu, s, d);
        if (l >= d) s += u;
    }
    int excl = s - nb;
    bool hit = (l < N_EXPERTS) && (rem >= excl) && (rem < excl + nb);
    unsigned hm = __ballot_sync(0xffffffffu, hit);
    if (hm == 0) return;                                // beyond total work (uniform)
    int el  = __ffs(hm) - 1;
    int e   = el;
    int n   = __shfl_sync(0xffffffffu, cnt, el);
    int base = (rem - __shfl_sync(0xffffffffu, excl, el)) * TILE;

    // ---- phase 1: issue ALL independent LDGs (weights), then gather ----
    float w1r[8], w0r[8];
    #pragma unroll
    for (int q = 0; q < 8; q++) {
        int i = tid + q * CTPB;
        w1r[q] = W1[e * DIM * DIM + i];
        w0r[q] = W0[e * DIM * DIM + i];
    }
    float bv1 = 0.0f, bv0 = 0.0f;
    if (tid < DIM) {
        bv1 = b1[e * DIM + tid];
        bv0 = b0[e * DIM + tid];
    }
    int slot = base + tid;
    int tok = (slot < n) ? g_bucket[e * MAXB + slot] : -1;   // coalesced

    // quad-cooperative gather: quad (lanes l4..l4+3) owns warp rows l4..l4+3
    int t4 = l & 3;
    int l4 = l & ~3;
    int tj[4];
    #pragma unroll
    for (int j = 0; j < 4; j++)
        tj[j] = __shfl_sync(0xffffffffu, tok, l4 + j);
    float v[4][8];
    #pragma unroll
    for (int j = 0; j < 4; j++) {
        #pragma unroll
        for (int k = 0; k < 8; k++) v[j][k] = 0.0f;
        if (tj[j] >= 0) {
            const float4* xp = (const float4*)(x + (size_t)tj[j] * DIM + t4 * 8);
            float4 a = xp[0], b2 = xp[1];
            v[j][0] = a.x;  v[j][1] = a.y;  v[j][2] = a.z;  v[j][3] = a.w;
            v[j][4] = b2.x; v[j][5] = b2.y; v[j][6] = b2.z; v[j][7] = b2.w;
        }
    }

    // ---- phase 2: convert + STS (operands have landed) ----
    #pragma unroll
    for (int q = 0; q < 8; q++) {
        int i = tid + q * CTPB;
        int o = i >> 5, k = i & 31;
        __nv_bfloat16 h1 = __float2bfloat16(w1r[q]);
        sB1[o * ASTR + k]      = h1;
        sB1[o * ASTR + 32 + k] = __float2bfloat16(w1r[q] - __bfloat162float(h1));
        __nv_bfloat16 h0 = __float2bfloat16(w0r[q]);
        sB2[o * ASTR + k]      = h0;
        sB2[o * ASTR + 32 + k] = __float2bfloat16(w0r[q] - __bfloat162float(h0));
    }
    if (tid < DIM) {
        sb1[tid] = bv1;
        sb0[tid] = bv0;
    }
    sTok[tid] = tok;
    #pragma unroll
    for (int j = 0; j < 4; j++) {
        int R = (tid & ~31) + l4 + j;     // tile row
        uint32_t hi[4], lo[4];
        split2(v[j][0], v[j][1], hi[0], lo[0]);
        split2(v[j][2], v[j][3], hi[1], lo[1]);
        split2(v[j][4], v[j][5], hi[2], lo[2]);
        split2(v[j][6], v[j][7], hi[3], lo[3]);
        *(uint4*)&sA[R * ASTR + 8 * t4]      = make_uint4(hi[0], hi[1], hi[2], hi[3]);
        *(uint4*)&sA[R * ASTR + 32 + 8 * t4] = make_uint4(lo[0], lo[1], lo[2], lo[3]);
    }
    __syncthreads();   // the ONLY block barrier

    // ---- fragment geometry ----
    int w  = tid >> 5;
    int g  = l >> 2;           // 0..7
    // CSE-friendly order: products (Ahi,Bhi k0),(Alo,Bhi k0),(Ahi,Blo k0),
    //                     (Ahi,Bhi k1),(Alo,Bhi k1),(Ahi,Blo k1)
    const int kA[6] = {0, 32, 0, 16, 48, 16};
    const int kB[6] = {0, 0, 32, 16, 16, 48};

    float acc[2][4][4];

    // ======================= layer 1 =======================
    #pragma unroll
    for (int mt = 0; mt < 2; mt++)
        #pragma unroll
        for (int nt = 0; nt < 4; nt++) {
            float2 bv = *(const float2*)&sb1[nt * 8 + 2 * t4];
            acc[mt][nt][0] = bv.x; acc[mt][nt][1] = bv.y;
            acc[mt][nt][2] = bv.x; acc[mt][nt][3] = bv.y;
        }
    #pragma unroll
    for (int ks = 0; ks < 6; ks++) {
        uint32_t bf[4][2];
        #pragma unroll
        for (int nt = 0; nt < 4; nt++) {
            bf[nt][0] = *(const uint32_t*)&sB1[(nt * 8 + g) * ASTR + kB[ks] + 2 * t4];
            bf[nt][1] = *(const uint32_t*)&sB1[(nt * 8 + g) * ASTR + kB[ks] + 2 * t4 + 8];
        }
        #pragma unroll
        for (int mt = 0; mt < 2; mt++) {
            int r0 = w * 32 + mt * 16 + g;
            uint32_t af[4];
            af[0] = *(const uint32_t*)&sA[r0       * ASTR + kA[ks] + 2 * t4];
            af[1] = *(const uint32_t*)&sA[(r0 + 8) * ASTR + kA[ks] + 2 * t4];
            af[2] = *(const uint32_t*)&sA[r0       * ASTR + kA[ks] + 2 * t4 + 8];
            af[3] = *(const uint32_t*)&sA[(r0 + 8) * ASTR + kA[ks] + 2 * t4 + 8];
            #pragma unroll
            for (int nt = 0; nt < 4; nt++) mma16816(acc[mt][nt], af, bf[nt]);
        }
    }

    // write h back into A tile (hi/lo) — warp-local rows only
    #pragma unroll
    for (int mt = 0; mt < 2; mt++) {
        int r0 = w * 32 + mt * 16 + g;
        #pragma unroll
        for (int nt = 0; nt < 4; nt++) {
            int c = nt * 8 + 2 * t4;
            uint32_t hi0, lo0, hi1, lo1;
            split2(acc[mt][nt][0], acc[mt][nt][1], hi0, lo0);
            split2(acc[mt][nt][2], acc[mt][nt][3], hi1, lo1);
            *(uint32_t*)&sA[r0 * ASTR + c]            = hi0;
            *(uint32_t*)&sA[r0 * ASTR + 32 + c]       = lo0;
            *(uint32_t*)&sA[(r0 + 8) * ASTR + c]      = hi1;
            *(uint32_t*)&sA[(r0 + 8) * ASTR + 32 + c] = lo1;
        }
    }
    __syncwarp();

    // ======================= layer 0 =======================
    #pragma unroll
    for (int mt = 0; mt < 2; mt++)
        #pragma unroll
        for (int nt = 0; nt < 4; nt++) {
            float2 bv = *(const float2*)&sb0[nt * 8 + 2 * t4];
            acc[mt][nt][0] = bv.x; acc[mt][nt][1] = bv.y;
            acc[mt][nt][2] = bv.x; acc[mt][nt][3] = bv.y;
        }
    #pragma unroll
    for (int ks = 0; ks < 6; ks++) {
        uint32_t bf[4][2];
        #pragma unroll
        for (int nt = 0; nt < 4; nt++) {
            bf[nt][0] = *(const uint32_t*)&sB2[(nt * 8 + g) * ASTR + kB[ks] + 2 * t4];
            bf[nt][1] = *(const uint32_t*)&sB2[(nt * 8 + g) * ASTR + kB[ks] + 2 * t4 + 8];
        }
        #pragma unroll
        for (int mt = 0; mt < 2; mt++) {
            int r0 = w * 32 + mt * 16 + g;
            uint32_t af[4];
            af[0] = *(const uint32_t*)&sA[r0       * ASTR + kA[ks] + 2 * t4];
            af[1] = *(const uint32_t*)&sA[(r0 + 8) * ASTR + kA[ks] + 2 * t4];
            af[2] = *(const uint32_t*)&sA[r0       * ASTR + kA[ks] + 2 * t4 + 8];
            af[3] = *(const uint32_t*)&sA[(r0 + 8) * ASTR + kA[ks] + 2 * t4 + 8];
            #pragma unroll
            for (int nt = 0; nt < 4; nt++) mma16816(acc[mt][nt], af, bf[nt]);
        }
    }

    // ---- epilogue: row sum-of-squares (4-lane bfly), normalize, store ----
    #pragma unroll
    for (int mt = 0; mt < 2; mt++) {
        int r0 = w * 32 + mt * 16 + g;
        float s0 = 0.0f, s1 = 0.0f;
        #pragma unroll
        for (int nt = 0; nt < 4; nt++) {
            s0 = fmaf(acc[mt][nt][0], acc[mt][nt][0], s0);
            s0 = fmaf(acc[mt][nt][1], acc[mt][nt][1], s0);
            s1 = fmaf(acc[mt][nt][2], acc[mt][nt][2], s1);
            s1 = fmaf(acc[mt][nt][3], acc[mt][nt][3], s1);
        }
        s0 += __shfl_xor_sync(0xffffffffu, s0, 1);
        s0 += __shfl_xor_sync(0xffffffffu, s0, 2);
        s1 += __shfl_xor_sync(0xffffffffu, s1, 1);
        s1 += __shfl_xor_sync(0xffffffffu, s1, 2);
        float inv0 = 1.0f / fmaxf(sqrtf(s0), 1e-12f);
        float inv1 = 1.0f / fmaxf(sqrtf(s1), 1e-12f);

        int u0 = sTok[r0];
        int u1 = sTok[r0 + 8];
        #pragma unroll
        for (int nt = 0; nt < 4; nt++) {
            int c = nt * 8 + 2 * t4;
            if (u0 >= 0) {
                float2 v2 = make_float2(acc[mt][nt][0] * inv0, acc[mt][nt][1] * inv0);
                *(float2*)(out + (size_t)u0 * DIM + c) = v2;
            }
            if (u1 >= 0) {
                float2 v2 = make_float2(acc[mt][nt][2] * inv1, acc[mt][nt][3] * inv1);
                *(float2*)(out + (size_t)u1 * DIM + c) = v2;
            }
        }
    }
}

// ---------------- launch -------------------------------------------------
extern "C" void kernel_launch(void* const* d_in, const int* in_sizes, int n_in,
                              void* d_out, int out_size) {
    const float* x  = (const float*)d_in[0];
    const float* W1 = (const float*)d_in[1];
    const float* b1 = (const float*)d_in[2];
    const float* W0 = (const float*)d_in[3];
    const float* b0 = (const float*)d_in[4];
    const void*  pos = d_in[5];
    float* out = (float*)d_out;

    int B = in_sizes[0] / DIM;
    if (B > MAXB) B = MAXB;
    int nblk_b = (B + 2 * TPB_B - 1) / (2 * TPB_B);
    int nblk_c = (B + TILE - 1) / TILE + N_EXPERTS - 1;

    void* cnt_ptr = nullptr;
    cudaGetSymbolAddress(&cnt_ptr, g_cnt);
    cudaMemsetAsync(cnt_ptr, 0, N_EXPERTS * sizeof(int), 0);

    k_bucket<<<nblk_b, TPB_B>>>(pos, B);
    k_compute<<<nblk_c, CTPB>>>(x, W1, b1, W0, b0, out);
}

// round 15
// speedup vs baseline: 1.0735x; 1.0467x over previous
#include <cuda_runtime.h>
#include <cuda_bf16.h>
#include <stdint.h>

#define N_EXPERTS 20
#define DIM 32
#define MAXB (1 << 17)     // 131072
#define TPB_B 256
#define TILE 128           // tokens per compute CTA
#define CTPB 128
#define ASTR 72            // tile row stride in bf16 elems (144B, conflict-free)

__device__ int g_cnt[N_EXPERTS];
__device__ int g_done = 0;
__device__ int g_bucket[N_EXPERTS * MAXB];

// ---- kernel 1: fused bucket, 2 tokens/thread ----------------------------
__global__ void __launch_bounds__(TPB_B) k_bucket(const void* __restrict__ pos, int B) {
    __shared__ int sh[N_EXPERTS];
    __shared__ int sbase[N_EXPERTS];
    __shared__ int s_is64;

    if (threadIdx.x < N_EXPERTS) sh[threadIdx.x] = 0;
    if (threadIdx.x < 32) {
        // int64 pos => all odd 32-bit words are zero high-words (values < 20)
        int v = ((const int*)pos)[2 * threadIdx.x + 1];   // B >= 64 guaranteed
        unsigned nz = __ballot_sync(0xffffffffu, v != 0);
        if (threadIdx.x == 0) s_is64 = (nz == 0) ? 1 : 0;
    }
    __syncthreads();

    int lane = threadIdx.x & 31;
    int t0 = blockIdx.x * (2 * TPB_B) + threadIdx.x;
    int t1 = t0 + TPB_B;
    int e0 = -1, e1 = -1, r0 = 0, r1 = 0;
    bool v0 = (t0 < B), v1 = (t1 < B);
    if (v0) e0 = s_is64 ? (int)((const long long*)pos)[t0] : ((const int*)pos)[t0];
    if (v1) e1 = s_is64 ? (int)((const long long*)pos)[t1] : ((const int*)pos)[t1];

    {   // warp-aggregated smem hist, round 0
        unsigned mm = __match_any_sync(0xffffffffu, e0);
        int rank = __popc(mm & ((1u << lane) - 1));
        int leader = __ffs(mm) - 1;
        int wbase = 0;
        if (lane == leader && v0) wbase = atomicAdd(&sh[e0], __popc(mm));
        wbase = __shfl_sync(0xffffffffu, wbase, leader);
        r0 = wbase + rank;
    }
    {   // round 1
        unsigned mm = __match_any_sync(0xffffffffu, e1);
        int rank = __popc(mm & ((1u << lane) - 1));
        int leader = __ffs(mm) - 1;
        int wbase = 0;
        if (lane == leader && v1) wbase = atomicAdd(&sh[e1], __popc(mm));
        wbase = __shfl_sync(0xffffffffu, wbase, leader);
        r1 = wbase + rank;
    }

    __syncthreads();
    if (threadIdx.x < N_EXPERTS) {
        int c = sh[threadIdx.x];
        sbase[threadIdx.x] = c ? atomicAdd(&g_cnt[threadIdx.x], c) : 0;
    }
    __syncthreads();
    if (v0) g_bucket[e0 * MAXB + sbase[e0] + r0] = t0;
    if (v1) g_bucket[e1 * MAXB + sbase[e1] + r1] = t1;
}

// ---- mma.sync wrapper ----------------------------------------------------
__device__ __forceinline__ void mma16816(float* c, const uint32_t* a, const uint32_t* b) {
    asm volatile(
        "mma.sync.aligned.m16n8k16.row.col.f32.bf16.bf16.f32 "
        "{%0,%1,%2,%3}, {%4,%5,%6,%7}, {%8,%9}, {%0,%1,%2,%3};"
        : "+f"(c[0]), "+f"(c[1]), "+f"(c[2]), "+f"(c[3])
        : "r"(a[0]), "r"(a[1]), "r"(a[2]), "r"(a[3]), "r"(b[0]), "r"(b[1]));
}

// split one fp32 pair into hi/lo bf16
__device__ __forceinline__ void split2(float a, float b, uint32_t& hi, uint32_t& lo) {
    __nv_bfloat162 hp = __floats2bfloat162_rn(a, b);
    float ra = a - __bfloat162float(hp.x);
    float rb = b - __bfloat162float(hp.y);
    __nv_bfloat162 lp = __floats2bfloat162_rn(ra, rb);
    hi = *reinterpret_cast<uint32_t*>(&hp);
    lo = *reinterpret_cast<uint32_t*>(&lp);
}

// last-arriving CTA resets g_cnt/g_done for the next graph replay.
// Safe: every CTA's tid0 bumps g_done only after ALL its warps have consumed
// g_cnt (block barrier precedes the bump), so the resetter acts after all reads.
__device__ __forceinline__ void reset_counters_if_last() {
    int d = atomicAdd(&g_done, 1);
    if (d == (int)gridDim.x - 1) {
        g_done = 0;
        #pragma unroll
        for (int i = 0; i < N_EXPERTS; i++) g_cnt[i] = 0;
    }
}

// ---- kernel 2: HMMA compute (R11/R14 body + self-resetting counters) -----
__global__ void __launch_bounds__(CTPB, 6) k_compute(
    const float* __restrict__ x,
    const float* __restrict__ W1, const float* __restrict__ b1,
    const float* __restrict__ W0, const float* __restrict__ b0,
    float* __restrict__ out)
{
    __shared__ __align__(16) __nv_bfloat16 sA[TILE * ASTR];      // 18432 B
    __shared__ __align__(16) __nv_bfloat16 sB1[DIM * ASTR];      // 4608 B
    __shared__ __align__(16) __nv_bfloat16 sB2[DIM * ASTR];      // 4608 B
    __shared__ __align__(16) float sb1[DIM], sb0[DIM];
    __shared__ int sTok[TILE];

    int tid = threadIdx.x;
    int l   = tid & 31;

    // ---- block -> (expert, tile): parallel load + warp scan ----
    int rem = blockIdx.x;
    int cnt = (l < N_EXPERTS) ? g_cnt[l] : 0;          // one broadcast LDG
    int nb  = (cnt + TILE - 1) / TILE;
    int s = nb;
    #pragma unroll
    for (int d = 1; d < 32; d <<= 1) {
        int u = __shfl_up_sync(0xffffffffu, s, d);
        if (l >= d) s += u;
    }
    int excl = s - nb;
    bool hit = (l < N_EXPERTS) && (rem >= excl) && (rem < excl + nb);
    unsigned hm = __ballot_sync(0xffffffffu, hit);
    if (hm == 0) {                                      // beyond total work
        __syncthreads();                                // all warps have read g_cnt
        if (tid == 0) reset_counters_if_last();
        return;
    }
    int el  = __ffs(hm) - 1;
    int e   = el;
    int n   = __shfl_sync(0xffffffffu, cnt, el);
    int base = (rem - __shfl_sync(0xffffffffu, excl, el)) * TILE;

    // ---- phase 1: issue ALL independent LDGs (weights), then gather ----
    float w1r[8], w0r[8];
    #pragma unroll
    for (int q = 0; q < 8; q++) {
        int i = tid + q * CTPB;
        w1r[q] = W1[e * DIM * DIM + i];
        w0r[q] = W0[e * DIM * DIM + i];
    }
    float bv1 = 0.0f, bv0 = 0.0f;
    if (tid < DIM) {
        bv1 = b1[e * DIM + tid];
        bv0 = b0[e * DIM + tid];
    }
    int slot = base + tid;
    int tok = (slot < n) ? g_bucket[e * MAXB + slot] : -1;   // coalesced

    // quad-cooperative gather: quad (lanes l4..l4+3) owns warp rows l4..l4+3
    int t4 = l & 3;
    int l4 = l & ~3;
    int tj[4];
    #pragma unroll
    for (int j = 0; j < 4; j++)
        tj[j] = __shfl_sync(0xffffffffu, tok, l4 + j);
    float v[4][8];
    #pragma unroll
    for (int j = 0; j < 4; j++) {
        #pragma unroll
        for (int k = 0; k < 8; k++) v[j][k] = 0.0f;
        if (tj[j] >= 0) {
            const float4* xp = (const float4*)(x + (size_t)tj[j] * DIM + t4 * 8);
            float4 a = xp[0], b2 = xp[1];
            v[j][0] = a.x;  v[j][1] = a.y;  v[j][2] = a.z;  v[j][3] = a.w;
            v[j][4] = b2.x; v[j][5] = b2.y; v[j][6] = b2.z; v[j][7] = b2.w;
        }
    }

    // ---- phase 2: convert + STS (operands have landed) ----
    #pragma unroll
    for (int q = 0; q < 8; q++) {
        int i = tid + q * CTPB;
        int o = i >> 5, k = i & 31;
        __nv_bfloat16 h1 = __float2bfloat16(w1r[q]);
        sB1[o * ASTR + k]      = h1;
        sB1[o * ASTR + 32 + k] = __float2bfloat16(w1r[q] - __bfloat162float(h1));
        __nv_bfloat16 h0 = __float2bfloat16(w0r[q]);
        sB2[o * ASTR + k]      = h0;
        sB2[o * ASTR + 32 + k] = __float2bfloat16(w0r[q] - __bfloat162float(h0));
    }
    if (tid < DIM) {
        sb1[tid] = bv1;
        sb0[tid] = bv0;
    }
    sTok[tid] = tok;
    #pragma unroll
    for (int j = 0; j < 4; j++) {
        int R = (tid & ~31) + l4 + j;     // tile row
        uint32_t hi[4], lo[4];
        split2(v[j][0], v[j][1], hi[0], lo[0]);
        split2(v[j][2], v[j][3], hi[1], lo[1]);
        split2(v[j][4], v[j][5], hi[2], lo[2]);
        split2(v[j][6], v[j][7], hi[3], lo[3]);
        *(uint4*)&sA[R * ASTR + 8 * t4]      = make_uint4(hi[0], hi[1], hi[2], hi[3]);
        *(uint4*)&sA[R * ASTR + 32 + 8 * t4] = make_uint4(lo[0], lo[1], lo[2], lo[3]);
    }
    __syncthreads();   // publishes sB1/sB2/biases; also orders the g_cnt reads
    if (tid == 0) reset_counters_if_last();

    // ---- fragment geometry ----
    int w  = tid >> 5;
    int g  = l >> 2;           // 0..7
    const int kA[6] = {0, 16, 32, 48, 0, 16};
    const int kB[6] = {0, 16, 0, 16, 32, 48};

    float acc[2][4][4];

    // ======================= layer 1 =======================
    #pragma unroll
    for (int mt = 0; mt < 2; mt++)
        #pragma unroll
        for (int nt = 0; nt < 4; nt++) {
            float2 bv = *(const float2*)&sb1[nt * 8 + 2 * t4];
            acc[mt][nt][0] = bv.x; acc[mt][nt][1] = bv.y;
            acc[mt][nt][2] = bv.x; acc[mt][nt][3] = bv.y;
        }
    #pragma unroll
    for (int ks = 0; ks < 6; ks++) {
        uint32_t bf[4][2];
        #pragma unroll
        for (int nt = 0; nt < 4; nt++) {
            bf[nt][0] = *(const uint32_t*)&sB1[(nt * 8 + g) * ASTR + kB[ks] + 2 * t4];
            bf[nt][1] = *(const uint32_t*)&sB1[(nt * 8 + g) * ASTR + kB[ks] + 2 * t4 + 8];
        }
        #pragma unroll
        for (int mt = 0; mt < 2; mt++) {
            int r0 = w * 32 + mt * 16 + g;
            uint32_t af[4];
            af[0] = *(const uint32_t*)&sA[r0       * ASTR + kA[ks] + 2 * t4];
            af[1] = *(const uint32_t*)&sA[(r0 + 8) * ASTR + kA[ks] + 2 * t4];
            af[2] = *(const uint32_t*)&sA[r0       * ASTR + kA[ks] + 2 * t4 + 8];
            af[3] = *(const uint32_t*)&sA[(r0 + 8) * ASTR + kA[ks] + 2 * t4 + 8];
            #pragma unroll
            for (int nt = 0; nt < 4; nt++) mma16816(acc[mt][nt], af, bf[nt]);
        }
    }

    // write h back into A tile (hi/lo) — warp-local rows only
    #pragma unroll
    for (int mt = 0; mt < 2; mt++) {
        int r0 = w * 32 + mt * 16 + g;
        #pragma unroll
        for (int nt = 0; nt < 4; nt++) {
            int c = nt * 8 + 2 * t4;
            uint32_t hi0, lo0, hi1, lo1;
            split2(acc[mt][nt][0], acc[mt][nt][1], hi0, lo0);
            split2(acc[mt][nt][2], acc[mt][nt][3], hi1, lo1);
            *(uint32_t*)&sA[r0 * ASTR + c]            = hi0;
            *(uint32_t*)&sA[r0 * ASTR + 32 + c]       = lo0;
            *(uint32_t*)&sA[(r0 + 8) * ASTR + c]      = hi1;
            *(uint32_t*)&sA[(r0 + 8) * ASTR + 32 + c] = lo1;
        }
    }
    __syncwarp();

    // ======================= layer 0 =======================
    #pragma unroll
    for (int mt = 0; mt < 2; mt++)
        #pragma unroll
        for (int nt = 0; nt < 4; nt++) {
            float2 bv = *(const float2*)&sb0[nt * 8 + 2 * t4];
            acc[mt][nt][0] = bv.x; acc[mt][nt][1] = bv.y;
            acc[mt][nt][2] = bv.x; acc[mt][nt][3] = bv.y;
        }
    #pragma unroll
    for (int ks = 0; ks < 6; ks++) {
        uint32_t bf[4][2];
        #pragma unroll
        for (int nt = 0; nt < 4; nt++) {
            bf[nt][0] = *(const uint32_t*)&sB2[(nt * 8 + g) * ASTR + kB[ks] + 2 * t4];
            bf[nt][1] = *(const uint32_t*)&sB2[(nt * 8 + g) * ASTR + kB[ks] + 2 * t4 + 8];
        }
        #pragma unroll
        for (int mt = 0; mt < 2; mt++) {
            int r0 = w * 32 + mt * 16 + g;
            uint32_t af[4];
            af[0] = *(const uint32_t*)&sA[r0       * ASTR + kA[ks] + 2 * t4];
            af[1] = *(const uint32_t*)&sA[(r0 + 8) * ASTR + kA[ks] + 2 * t4];
            af[2] = *(const uint32_t*)&sA[r0       * ASTR + kA[ks] + 2 * t4 + 8];
            af[3] = *(const uint32_t*)&sA[(r0 + 8) * ASTR + kA[ks] + 2 * t4 + 8];
            #pragma unroll
            for (int nt = 0; nt < 4; nt++) mma16816(acc[mt][nt], af, bf[nt]);
        }
    }

    // ---- epilogue: row sum-of-squares (4-lane bfly), normalize, store ----
    #pragma unroll
    for (int mt = 0; mt < 2; mt++) {
        int r0 = w * 32 + mt * 16 + g;
        float s0 = 0.0f, s1 = 0.0f;
        #pragma unroll
        for (int nt = 0; nt < 4; nt++) {
            s0 = fmaf(acc[mt][nt][0], acc[mt][nt][0], s0);
            s0 = fmaf(acc[mt][nt][1], acc[mt][nt][1], s0);
            s1 = fmaf(acc[mt][nt][2], acc[mt][nt][2], s1);
            s1 = fmaf(acc[mt][nt][3], acc[mt][nt][3], s1);
        }
        s0 += __shfl_xor_sync(0xffffffffu, s0, 1);
        s0 += __shfl_xor_sync(0xffffffffu, s0, 2);
        s1 += __shfl_xor_sync(0xffffffffu, s1, 1);
        s1 += __shfl_xor_sync(0xffffffffu, s1, 2);
        float inv0 = 1.0f / fmaxf(sqrtf(s0), 1e-12f);
        float inv1 = 1.0f / fmaxf(sqrtf(s1), 1e-12f);

        int u0 = sTok[r0];
        int u1 = sTok[r0 + 8];
        #pragma unroll
        for (int nt = 0; nt < 4; nt++) {
            int c = nt * 8 + 2 * t4;
            if (u0 >= 0) {
                float2 v2 = make_float2(acc[mt][nt][0] * inv0, acc[mt][nt][1] * inv0);
                *(float2*)(out + (size_t)u0 * DIM + c) = v2;
            }
            if (u1 >= 0) {
                float2 v2 = make_float2(acc[mt][nt][2] * inv1, acc[mt][nt][3] * inv1);
                *(float2*)(out + (size_t)u1 * DIM + c) = v2;
            }
        }
    }
}

// ---------------- launch -------------------------------------------------
extern "C" void kernel_launch(void* const* d_in, const int* in_sizes, int n_in,
                              void* d_out, int out_size) {
    const float* x  = (const float*)d_in[0];
    const float* W1 = (const float*)d_in[1];
    const float* b1 = (const float*)d_in[2];
    const float* W0 = (const float*)d_in[3];
    const float* b0 = (const float*)d_in[4];
    const void*  pos = d_in[5];
    float* out = (float*)d_out;

    int B = in_sizes[0] / DIM;
    if (B > MAXB) B = MAXB;
    int nblk_b = (B + 2 * TPB_B - 1) / (2 * TPB_B);
    int nblk_c = (B + TILE - 1) / TILE + N_EXPERTS - 1;

    // g_cnt is zeroed by the previous launch's k_compute (self-resetting);
    // initial state comes from static initialization. No memset node needed.
    k_bucket<<<nblk_b, TPB_B>>>(pos, B);
    k_compute<<<nblk_c, CTPB>>>(x, W1, b1, W0, b0, out);
}

// round 16
// speedup vs baseline: 1.0861x; 1.0118x over previous
#include <cuda_runtime.h>
#include <cuda_bf16.h>
#include <stdint.h>

#define N_EXPERTS 20
#define DIM 32
#define MAXB (1 << 17)     // 131072
#define TPB_B 256
#define TOKB 4             // tokens per bucket thread
#define TILE 128           // tokens per compute CTA
#define CTPB 128
#define ASTR 72            // tile row stride in bf16 elems (144B, conflict-free)
#define FSTR 36            // float-tile row stride in floats (same 144B)

__device__ int g_cnt[N_EXPERTS];
__device__ int g_done = 0;
__device__ int g_bucket[N_EXPERTS * MAXB];

// ---- kernel 1: fused bucket, 4 tokens/thread ----------------------------
__global__ void __launch_bounds__(TPB_B) k_bucket(const void* __restrict__ pos, int B) {
    __shared__ int sh[N_EXPERTS];
    __shared__ int sbase[N_EXPERTS];
    __shared__ int s_is64;

    if (threadIdx.x < N_EXPERTS) sh[threadIdx.x] = 0;
    if (threadIdx.x < 32) {
        // int64 pos => all odd 32-bit words are zero high-words (values < 20)
        int v = ((const int*)pos)[2 * threadIdx.x + 1];   // B >= 64 guaranteed
        unsigned nz = __ballot_sync(0xffffffffu, v != 0);
        if (threadIdx.x == 0) s_is64 = (nz == 0) ? 1 : 0;
    }
    __syncthreads();

    int lane = threadIdx.x & 31;
    int tt[TOKB], ee[TOKB], rr[TOKB];
    bool vv[TOKB];
    #pragma unroll
    for (int k = 0; k < TOKB; k++) {
        tt[k] = blockIdx.x * (TOKB * TPB_B) + k * TPB_B + threadIdx.x;
        vv[k] = (tt[k] < B);
        ee[k] = vv[k]
              ? (s_is64 ? (int)((const long long*)pos)[tt[k]] : ((const int*)pos)[tt[k]])
              : -1;
    }
    #pragma unroll
    for (int k = 0; k < TOKB; k++) {
        unsigned mm = __match_any_sync(0xffffffffu, ee[k]);
        int rank = __popc(mm & ((1u << lane) - 1));
        int leader = __ffs(mm) - 1;
        int wbase = 0;
        if (lane == leader && vv[k]) wbase = atomicAdd(&sh[ee[k]], __popc(mm));
        wbase = __shfl_sync(0xffffffffu, wbase, leader);
        rr[k] = wbase + rank;
    }

    __syncthreads();
    if (threadIdx.x < N_EXPERTS) {
        int c = sh[threadIdx.x];
        sbase[threadIdx.x] = c ? atomicAdd(&g_cnt[threadIdx.x], c) : 0;
    }
    __syncthreads();
    #pragma unroll
    for (int k = 0; k < TOKB; k++)
        if (vv[k]) g_bucket[ee[k] * MAXB + sbase[ee[k]] + rr[k]] = tt[k];
}

// ---- mma.sync wrapper ----------------------------------------------------
__device__ __forceinline__ void mma16816(float* c, const uint32_t* a, const uint32_t* b) {
    asm volatile(
        "mma.sync.aligned.m16n8k16.row.col.f32.bf16.bf16.f32 "
        "{%0,%1,%2,%3}, {%4,%5,%6,%7}, {%8,%9}, {%0,%1,%2,%3};"
        : "+f"(c[0]), "+f"(c[1]), "+f"(c[2]), "+f"(c[3])
        : "r"(a[0]), "r"(a[1]), "r"(a[2]), "r"(a[3]), "r"(b[0]), "r"(b[1]));
}

// split one fp32 pair into hi/lo bf16
__device__ __forceinline__ void split2(float a, float b, uint32_t& hi, uint32_t& lo) {
    __nv_bfloat162 hp = __floats2bfloat162_rn(a, b);
    float ra = a - __bfloat162float(hp.x);
    float rb = b - __bfloat162float(hp.y);
    __nv_bfloat162 lp = __floats2bfloat162_rn(ra, rb);
    hi = *reinterpret_cast<uint32_t*>(&hp);
    lo = *reinterpret_cast<uint32_t*>(&lp);
}

// last-arriving CTA resets g_cnt/g_done for the next graph replay.
__device__ __forceinline__ void reset_counters_if_last() {
    int d = atomicAdd(&g_done, 1);
    if (d == (int)gridDim.x - 1) {
        g_done = 0;
        #pragma unroll
        for (int i = 0; i < N_EXPERTS; i++) g_cnt[i] = 0;
    }
}

// ---- kernel 2: HMMA compute + quad-cooperative epilogue stores -----------
__global__ void __launch_bounds__(CTPB, 6) k_compute(
    const float* __restrict__ x,
    const float* __restrict__ W1, const float* __restrict__ b1,
    const float* __restrict__ W0, const float* __restrict__ b0,
    float* __restrict__ out)
{
    __shared__ __align__(16) __nv_bfloat16 sA[TILE * ASTR];      // 18432 B
    __shared__ __align__(16) __nv_bfloat16 sB1[DIM * ASTR];      // 4608 B
    __shared__ __align__(16) __nv_bfloat16 sB2[DIM * ASTR];      // 4608 B
    __shared__ __align__(16) float sb1[DIM], sb0[DIM];
    __shared__ int sTok[TILE];

    int tid = threadIdx.x;
    int l   = tid & 31;

    // ---- block -> (expert, tile): parallel load + warp scan ----
    int rem = blockIdx.x;
    int cnt = (l < N_EXPERTS) ? g_cnt[l] : 0;          // one broadcast LDG
    int nb  = (cnt + TILE - 1) / TILE;
    int s = nb;
    #pragma unroll
    for (int d = 1; d < 32; d <<= 1) {
        int u = __shfl_up_sync(0xffffffffu, s, d);
        if (l >= d) s += u;
    }
    int excl = s - nb;
    bool hit = (l < N_EXPERTS) && (rem >= excl) && (rem < excl + nb);
    unsigned hm = __ballot_sync(0xffffffffu, hit);
    if (hm == 0) {                                      // beyond total work
        __syncthreads();                                // all warps have read g_cnt
        if (tid == 0) reset_counters_if_last();
        return;
    }
    int el  = __ffs(hm) - 1;
    int e   = el;
    int n   = __shfl_sync(0xffffffffu, cnt, el);
    int base = (rem - __shfl_sync(0xffffffffu, excl, el)) * TILE;

    // ---- phase 1: issue ALL independent LDGs (weights), then gather ----
    float w1r[8], w0r[8];
    #pragma unroll
    for (int q = 0; q < 8; q++) {
        int i = tid + q * CTPB;
        w1r[q] = W1[e * DIM * DIM + i];
        w0r[q] = W0[e * DIM * DIM + i];
    }
    float bv1 = 0.0f, bv0 = 0.0f;
    if (tid < DIM) {
        bv1 = b1[e * DIM + tid];
        bv0 = b0[e * DIM + tid];
    }
    int slot = base + tid;
    int tok = (slot < n) ? g_bucket[e * MAXB + slot] : -1;   // coalesced

    // quad-cooperative gather: quad (lanes l4..l4+3) owns warp rows l4..l4+3
    int t4 = l & 3;
    int l4 = l & ~3;
    int tj[4];
    #pragma unroll
    for (int j = 0; j < 4; j++)
        tj[j] = __shfl_sync(0xffffffffu, tok, l4 + j);
    float v[4][8];
    #pragma unroll
    for (int j = 0; j < 4; j++) {
        #pragma unroll
        for (int k = 0; k < 8; k++) v[j][k] = 0.0f;
        if (tj[j] >= 0) {
            const float4* xp = (const float4*)(x + (size_t)tj[j] * DIM + t4 * 8);
            float4 a = xp[0], b2 = xp[1];
            v[j][0] = a.x;  v[j][1] = a.y;  v[j][2] = a.z;  v[j][3] = a.w;
            v[j][4] = b2.x; v[j][5] = b2.y; v[j][6] = b2.z; v[j][7] = b2.w;
        }
    }

    // ---- phase 2: convert + STS (operands have landed) ----
    #pragma unroll
    for (int q = 0; q < 8; q++) {
        int i = tid + q * CTPB;
        int o = i >> 5, k = i & 31;
        __nv_bfloat16 h1 = __float2bfloat16(w1r[q]);
        sB1[o * ASTR + k]      = h1;
        sB1[o * ASTR + 32 + k] = __float2bfloat16(w1r[q] - __bfloat162float(h1));
        __nv_bfloat16 h0 = __float2bfloat16(w0r[q]);
        sB2[o * ASTR + k]      = h0;
        sB2[o * ASTR + 32 + k] = __float2bfloat16(w0r[q] - __bfloat162float(h0));
    }
    if (tid < DIM) {
        sb1[tid] = bv1;
        sb0[tid] = bv0;
    }
    sTok[tid] = tok;
    #pragma unroll
    for (int j = 0; j < 4; j++) {
        int R = (tid & ~31) + l4 + j;     // tile row
        uint32_t hi[4], lo[4];
        split2(v[j][0], v[j][1], hi[0], lo[0]);
        split2(v[j][2], v[j][3], hi[1], lo[1]);
        split2(v[j][4], v[j][5], hi[2], lo[2]);
        split2(v[j][6], v[j][7], hi[3], lo[3]);
        *(uint4*)&sA[R * ASTR + 8 * t4]      = make_uint4(hi[0], hi[1], hi[2], hi[3]);
        *(uint4*)&sA[R * ASTR + 32 + 8 * t4] = make_uint4(lo[0], lo[1], lo[2], lo[3]);
    }
    __syncthreads();   // publishes sB1/sB2/biases; also orders the g_cnt reads
    if (tid == 0) reset_counters_if_last();

    // ---- fragment geometry ----
    int w  = tid >> 5;
    int g  = l >> 2;           // 0..7
    const int kA[6] = {0, 16, 32, 48, 0, 16};
    const int kB[6] = {0, 16, 0, 16, 32, 48};

    float acc[2][4][4];

    // ======================= layer 1 =======================
    #pragma unroll
    for (int mt = 0; mt < 2; mt++)
        #pragma unroll
        for (int nt = 0; nt < 4; nt++) {
            float2 bv = *(const float2*)&sb1[nt * 8 + 2 * t4];
            acc[mt][nt][0] = bv.x; acc[mt][nt][1] = bv.y;
            acc[mt][nt][2] = bv.x; acc[mt][nt][3] = bv.y;
        }
    #pragma unroll
    for (int ks = 0; ks < 6; ks++) {
        uint32_t bf[4][2];
        #pragma unroll
        for (int nt = 0; nt < 4; nt++) {
            bf[nt][0] = *(const uint32_t*)&sB1[(nt * 8 + g) * ASTR + kB[ks] + 2 * t4];
            bf[nt][1] = *(const uint32_t*)&sB1[(nt * 8 + g) * ASTR + kB[ks] + 2 * t4 + 8];
        }
        #pragma unroll
        for (int mt = 0; mt < 2; mt++) {
            int r0 = w * 32 + mt * 16 + g;
            uint32_t af[4];
            af[0] = *(const uint32_t*)&sA[r0       * ASTR + kA[ks] + 2 * t4];
            af[1] = *(const uint32_t*)&sA[(r0 + 8) * ASTR + kA[ks] + 2 * t4];
            af[2] = *(const uint32_t*)&sA[r0       * ASTR + kA[ks] + 2 * t4 + 8];
            af[3] = *(const uint32_t*)&sA[(r0 + 8) * ASTR + kA[ks] + 2 * t4 + 8];
            #pragma unroll
            for (int nt = 0; nt < 4; nt++) mma16816(acc[mt][nt], af, bf[nt]);
        }
    }

    // write h back into A tile (hi/lo) — warp-local rows only
    #pragma unroll
    for (int mt = 0; mt < 2; mt++) {
        int r0 = w * 32 + mt * 16 + g;
        #pragma unroll
        for (int nt = 0; nt < 4; nt++) {
            int c = nt * 8 + 2 * t4;
            uint32_t hi0, lo0, hi1, lo1;
            split2(acc[mt][nt][0], acc[mt][nt][1], hi0, lo0);
            split2(acc[mt][nt][2], acc[mt][nt][3], hi1, lo1);
            *(uint32_t*)&sA[r0 * ASTR + c]            = hi0;
            *(uint32_t*)&sA[r0 * ASTR + 32 + c]       = lo0;
            *(uint32_t*)&sA[(r0 + 8) * ASTR + c]      = hi1;
            *(uint32_t*)&sA[(r0 + 8) * ASTR + 32 + c] = lo1;
        }
    }
    __syncwarp();

    // ======================= layer 0 =======================
    #pragma unroll
    for (int mt = 0; mt < 2; mt++)
        #pragma unroll
        for (int nt = 0; nt < 4; nt++) {
            float2 bv = *(const float2*)&sb0[nt * 8 + 2 * t4];
            acc[mt][nt][0] = bv.x; acc[mt][nt][1] = bv.y;
            acc[mt][nt][2] = bv.x; acc[mt][nt][3] = bv.y;
        }
    #pragma unroll
    for (int ks = 0; ks < 6; ks++) {
        uint32_t bf[4][2];
        #pragma unroll
        for (int nt = 0; nt < 4; nt++) {
            bf[nt][0] = *(const uint32_t*)&sB2[(nt * 8 + g) * ASTR + kB[ks] + 2 * t4];
            bf[nt][1] = *(const uint32_t*)&sB2[(nt * 8 + g) * ASTR + kB[ks] + 2 * t4 + 8];
        }
        #pragma unroll
        for (int mt = 0; mt < 2; mt++) {
            int r0 = w * 32 + mt * 16 + g;
            uint32_t af[4];
            af[0] = *(const uint32_t*)&sA[r0       * ASTR + kA[ks] + 2 * t4];
            af[1] = *(const uint32_t*)&sA[(r0 + 8) * ASTR + kA[ks] + 2 * t4];
            af[2] = *(const uint32_t*)&sA[r0       * ASTR + kA[ks] + 2 * t4 + 8];
            af[3] = *(const uint32_t*)&sA[(r0 + 8) * ASTR + kA[ks] + 2 * t4 + 8];
            #pragma unroll
            for (int nt = 0; nt < 4; nt++) mma16816(acc[mt][nt], af, bf[nt]);
        }
    }

    // ---- epilogue: norms -> scaled float tile (overlays sA) -> quad STG ----
    // Warp w's float rows (stride 36 floats = 144B) exactly overlay its own
    // bf16 A rows; all of this warp's sA reads are complete (in-order warp),
    // so only __syncwarp ordering is needed.
    float* sAf = (float*)sA;
    #pragma unroll
    for (int mt = 0; mt < 2; mt++) {
        int r0 = w * 32 + mt * 16 + g;
        float s0 = 0.0f, s1 = 0.0f;
        #pragma unroll
        for (int nt = 0; nt < 4; nt++) {
            s0 = fmaf(acc[mt][nt][0], acc[mt][nt][0], s0);
            s0 = fmaf(acc[mt][nt][1], acc[mt][nt][1], s0);
            s1 = fmaf(acc[mt][nt][2], acc[mt][nt][2], s1);
            s1 = fmaf(acc[mt][nt][3], acc[mt][nt][3], s1);
        }
        s0 += __shfl_xor_sync(0xffffffffu, s0, 1);
        s0 += __shfl_xor_sync(0xffffffffu, s0, 2);
        s1 += __shfl_xor_sync(0xffffffffu, s1, 1);
        s1 += __shfl_xor_sync(0xffffffffu, s1, 2);
        float inv0 = 1.0f / fmaxf(sqrtf(s0), 1e-12f);
        float inv1 = 1.0f / fmaxf(sqrtf(s1), 1e-12f);

        #pragma unroll
        for (int nt = 0; nt < 4; nt++) {
            int c = nt * 8 + 2 * t4;
            *(float2*)&sAf[r0 * FSTR + c] =
                make_float2(acc[mt][nt][0] * inv0, acc[mt][nt][1] * inv0);
            *(float2*)&sAf[(r0 + 8) * FSTR + c] =
                make_float2(acc[mt][nt][2] * inv1, acc[mt][nt][3] * inv1);
        }
    }
    __syncwarp();

    // quad-cooperative store: quad owns rows l4..l4+3, lane t4 covers
    // bytes [32*t4, 32*t4+32) of each row -> 8 lines per STG.128 instr.
    #pragma unroll
    for (int j = 0; j < 4; j++) {
        int R = (tid & ~31) + l4 + j;
        int u = sTok[R];
        if (u >= 0) {
            float4 a = *(float4*)&sAf[R * FSTR + 8 * t4];
            float4 b2 = *(float4*)&sAf[R * FSTR + 8 * t4 + 4];
            float4* op = (float4*)(out + (size_t)u * DIM + 8 * t4);
            op[0] = a;
            op[1] = b2;
        }
    }
}

// ---------------- launch -------------------------------------------------
extern "C" void kernel_launch(void* const* d_in, const int* in_sizes, int n_in,
                              void* d_out, int out_size) {
    const float* x  = (const float*)d_in[0];
    const float* W1 = (const float*)d_in[1];
    const float* b1 = (const float*)d_in[2];
    const float* W0 = (const float*)d_in[3];
    const float* b0 = (const float*)d_in[4];
    const void*  pos = d_in[5];
    float* out = (float*)d_out;

    int B = in_sizes[0] / DIM;
    if (B > MAXB) B = MAXB;
    int nblk_b = (B + TOKB * TPB_B - 1) / (TOKB * TPB_B);
    int nblk_c = (B + TILE - 1) / TILE + N_EXPERTS - 1;

    // g_cnt is zeroed by the previous launch's k_compute (self-resetting).
    k_bucket<<<nblk_b, TPB_B>>>(pos, B);
    k_compute<<<nblk_c, CTPB>>>(x, W1, b1, W0, b0, out);
}